// round 3
// baseline (speedup 1.0000x reference)
#include <cuda_runtime.h>
#include <cstdint>

// Max-unpool scatter, deterministic last-index-wins (matches reference).
//
// Round-3 scheme: 32-bit winner-index scratch, SELF-RESTORING zero invariant.
//   - __device__ globals are zero-initialized at module load -> scratch is
//     zero before the first call.
//   - compact_kernel zeroes each scratch word right after consuming it, so
//     every execution (correctness call + every graph replay) leaves scratch
//     all-zero for the next one. No separate zero pass. Deterministic: same
//     work, same output, every call.
//   K1 (scatter): for each input i: atomicMax(&scratch[pos[i]], i+1)
//                 pos streamed with __ldcs to keep scratch L2-resident.
//   K2 (compact): out[j] = w ? x[w-1] : 0 ; scratch[j] = 0 ;
//                 out written with __stcs (evict-first, never re-read).

#define N_OUT_CONST 25690112  // 32*112*112*64

__device__ unsigned int g_winner[N_OUT_CONST];

__global__ void scatter_kernel(const int4* __restrict__ p4, int n4, int n) {
    int t = blockIdx.x * blockDim.x + threadIdx.x;
    if (t < n4) {
        int4 pv = __ldcs(&p4[t]);   // stream pos: no reuse, don't pollute L2
        unsigned int base = (unsigned int)(t * 4);
        atomicMax(&g_winner[pv.x], base + 1u);
        atomicMax(&g_winner[pv.y], base + 2u);
        atomicMax(&g_winner[pv.z], base + 3u);
        atomicMax(&g_winner[pv.w], base + 4u);
    }
    // Tail (n % 4 != 0): first threads of block 0. (n is divisible by 4 for
    // this shape; kept for safety.)
    int tail_start = n4 * 4;
    int rem = n - tail_start;
    if (blockIdx.x == 0 && threadIdx.x < rem) {
        int i = tail_start + threadIdx.x;
        const int* p = reinterpret_cast<const int*>(p4);
        atomicMax(&g_winner[p[i]], (unsigned int)(i + 1));
    }
}

__global__ void compact_kernel(float* __restrict__ out,
                               const float* __restrict__ x,
                               int count8) {
    int t = blockIdx.x * blockDim.x + threadIdx.x;
    if (t >= count8) return;

    uint4* __restrict__ sp = reinterpret_cast<uint4*>(g_winner);
    float4* __restrict__ op = reinterpret_cast<float4*>(out);

    // 8 elements per thread: two uint4 winner words -> two float4 outputs.
    uint4 w0 = sp[2 * t + 0];
    uint4 w1 = sp[2 * t + 1];

    // Issue all 8 gathers before consuming (max MLP on random x reads).
    float4 o0, o1;
    o0.x = w0.x ? __ldg(&x[w0.x - 1u]) : 0.0f;
    o0.y = w0.y ? __ldg(&x[w0.y - 1u]) : 0.0f;
    o0.z = w0.z ? __ldg(&x[w0.z - 1u]) : 0.0f;
    o0.w = w0.w ? __ldg(&x[w0.w - 1u]) : 0.0f;
    o1.x = w1.x ? __ldg(&x[w1.x - 1u]) : 0.0f;
    o1.y = w1.y ? __ldg(&x[w1.y - 1u]) : 0.0f;
    o1.z = w1.z ? __ldg(&x[w1.z - 1u]) : 0.0f;
    o1.w = w1.w ? __ldg(&x[w1.w - 1u]) : 0.0f;

    // Zero-writeback: restores the all-zero invariant for the next call.
    // Lines are already dirty-resident in L2 from the read above.
    uint4 z = make_uint4(0u, 0u, 0u, 0u);
    sp[2 * t + 0] = z;
    sp[2 * t + 1] = z;

    // Streaming store: out is never re-read; don't evict scratch from L2.
    __stcs(&op[2 * t + 0], o0);
    __stcs(&op[2 * t + 1], o1);
}

extern "C" void kernel_launch(void* const* d_in, const int* in_sizes, int n_in,
                              void* d_out, int out_size) {
    const float* x = reinterpret_cast<const float*>(d_in[0]);
    const int* pos = reinterpret_cast<const int*>(d_in[1]);
    float* out     = reinterpret_cast<float*>(d_out);

    int n = in_sizes[0];        // 6,422,528
    int n4 = n / 4;
    int count8 = out_size / 8;  // 3,211,264 (out_size divisible by 8)

    const int T = 256;

    // K1: deterministic last-index-wins via 32-bit atomicMax (index only).
    //     Scratch is all-zero on entry (module-load init / prior compact).
    scatter_kernel<<<(n4 + T - 1) / T, T>>>(
        reinterpret_cast<const int4*>(pos), n4, n);

    // K2: gather winners' values, zero-fill empties, re-zero scratch,
    //     stream out.
    compact_kernel<<<(count8 + T - 1) / T, T>>>(out, x, count8);
}

// round 4
// speedup vs baseline: 1.0693x; 1.0693x over previous
#include <cuda_runtime.h>
#include <cstdint>

// Max-unpool scatter, deterministic last-index-wins (matches reference).
//
// Round-4 scheme: 2-pass range-split so the WHOLE working set is L2-resident.
//   Shared scratch: u32 winner-index for HALF the output (51.4 MB).
//   For k in {0,1}:
//     Z: zero scratch (L2-resident full-line stores; re-heats scratch in L2
//        immediately before the atomic phase)
//     S: scan all pos; if pos in [k*HALF,(k+1)*HALF): atomicMax(scr[p-lo], i+1)
//     C: out[lo+j] = w ? x[w-1] : 0   (__stcs: out never re-read, evict-first)
//   L2 budget: scratch 51.4 + x 25.7 + pos 25.7 = 103 MB < 126 MB L2.
//   Only mandatory DRAM stream in steady state: the 103 MB out write.

#define N_OUT_CONST 25690112          // 32*112*112*64
#define HALF_CONST  (N_OUT_CONST / 2) // 12,845,056

__device__ unsigned int g_winner[HALF_CONST];

__global__ void zero_scratch_kernel(int count4) {
    int idx = blockIdx.x * blockDim.x + threadIdx.x;
    if (idx < count4) {
        reinterpret_cast<uint4*>(g_winner)[idx] = make_uint4(0u, 0u, 0u, 0u);
    }
}

__device__ __forceinline__ void try_scatter(unsigned int p, unsigned int key,
                                            unsigned int lo, unsigned int hi) {
    if (p >= lo && p < hi) {
        atomicMax(&g_winner[p - lo], key);
    }
}

__global__ void scatter_range_kernel(const int4* __restrict__ p4, int n4, int n,
                                     unsigned int lo, unsigned int hi) {
    int t = blockIdx.x * blockDim.x + threadIdx.x;
    if (t < n4) {
        int4 pv = p4[t];   // default caching: pos is re-read by the other pass
        unsigned int base = (unsigned int)(t * 4);
        try_scatter((unsigned int)pv.x, base + 1u, lo, hi);
        try_scatter((unsigned int)pv.y, base + 2u, lo, hi);
        try_scatter((unsigned int)pv.z, base + 3u, lo, hi);
        try_scatter((unsigned int)pv.w, base + 4u, lo, hi);
    }
    int tail_start = n4 * 4;
    int rem = n - tail_start;
    if (blockIdx.x == 0 && threadIdx.x < rem) {
        int i = tail_start + threadIdx.x;
        const int* p = reinterpret_cast<const int*>(p4);
        try_scatter((unsigned int)p[i], (unsigned int)(i + 1), lo, hi);
    }
}

__global__ void compact_kernel(float* __restrict__ out,        // out + lo
                               const float* __restrict__ x,
                               int count8) {
    int t = blockIdx.x * blockDim.x + threadIdx.x;
    if (t >= count8) return;

    const uint4* __restrict__ sp = reinterpret_cast<const uint4*>(g_winner);
    float4* __restrict__ op = reinterpret_cast<float4*>(out);

    uint4 w0 = sp[2 * t + 0];
    uint4 w1 = sp[2 * t + 1];

    float4 o0, o1;
    o0.x = w0.x ? __ldg(&x[w0.x - 1u]) : 0.0f;
    o0.y = w0.y ? __ldg(&x[w0.y - 1u]) : 0.0f;
    o0.z = w0.z ? __ldg(&x[w0.z - 1u]) : 0.0f;
    o0.w = w0.w ? __ldg(&x[w0.w - 1u]) : 0.0f;
    o1.x = w1.x ? __ldg(&x[w1.x - 1u]) : 0.0f;
    o1.y = w1.y ? __ldg(&x[w1.y - 1u]) : 0.0f;
    o1.z = w1.z ? __ldg(&x[w1.z - 1u]) : 0.0f;
    o1.w = w1.w ? __ldg(&x[w1.w - 1u]) : 0.0f;

    // Streaming store: out is write-once; keep scratch/x/pos resident in L2.
    __stcs(&op[2 * t + 0], o0);
    __stcs(&op[2 * t + 1], o1);
}

extern "C" void kernel_launch(void* const* d_in, const int* in_sizes, int n_in,
                              void* d_out, int out_size) {
    const float* x = reinterpret_cast<const float*>(d_in[0]);
    const int* pos = reinterpret_cast<const int*>(d_in[1]);
    float* out     = reinterpret_cast<float*>(d_out);

    int n = in_sizes[0];            // 6,422,528
    int n4 = n / 4;
    unsigned int half = (unsigned int)(out_size / 2);  // 12,845,056
    int zcount4 = (int)(half / 4);
    int ccount8 = (int)(half / 8);

    const int T = 256;
    const int ZG = (zcount4 + T - 1) / T;
    const int SG = (n4 + T - 1) / T;
    const int CG = (ccount8 + T - 1) / T;

    for (int k = 0; k < 2; k++) {
        unsigned int lo = (unsigned int)k * half;
        unsigned int hi = lo + half;

        zero_scratch_kernel<<<ZG, T>>>(zcount4);
        scatter_range_kernel<<<SG, T>>>(
            reinterpret_cast<const int4*>(pos), n4, n, lo, hi);
        compact_kernel<<<CG, T>>>(out + lo, x, ccount8);
    }
}

// round 5
// speedup vs baseline: 1.2190x; 1.1400x over previous
#include <cuda_runtime.h>
#include <cstdint>

// Max-unpool scatter, deterministic last-index-wins (matches reference).
//
// Round-5: R2 topology (single pass, full-size winner scratch) with
// latency/ILP fixes per phase — metrics showed all three phases are
// latency-bound, not DRAM-BW-bound.
//   Z: zero scratch, 64B/thread (4x uint4)
//   S: atomicMax(scr[pos[i]], i+1), 8 atomics/thread, pos via __ldcs
//   C: out[j] = w ? x[w-1] : 0, 8/thread; scratch via __ldcs (dead after),
//      x via __ldg (L2-resident reuse), out via __stcs (write-once)

#define N_OUT_CONST 25690112  // 32*112*112*64

__device__ unsigned int g_winner[N_OUT_CONST];

// count16 = N_OUT/16 threads, each writes 4 consecutive uint4 (64B).
__global__ void zero_scratch_kernel(int count16) {
    int t = blockIdx.x * blockDim.x + threadIdx.x;
    if (t < count16) {
        uint4* p = reinterpret_cast<uint4*>(g_winner) + 4 * t;
        uint4 z = make_uint4(0u, 0u, 0u, 0u);
        p[0] = z; p[1] = z; p[2] = z; p[3] = z;
    }
}

// n8 = n/8 threads, each loads 2 int4 of pos and issues 8 atomics.
__global__ void scatter_kernel(const int4* __restrict__ p4, int n8) {
    int t = blockIdx.x * blockDim.x + threadIdx.x;
    if (t >= n8) return;
    int4 a = __ldcs(&p4[2 * t + 0]);
    int4 b = __ldcs(&p4[2 * t + 1]);
    unsigned int base = (unsigned int)(t * 8);
    atomicMax(&g_winner[a.x], base + 1u);
    atomicMax(&g_winner[a.y], base + 2u);
    atomicMax(&g_winner[a.z], base + 3u);
    atomicMax(&g_winner[a.w], base + 4u);
    atomicMax(&g_winner[b.x], base + 5u);
    atomicMax(&g_winner[b.y], base + 6u);
    atomicMax(&g_winner[b.z], base + 7u);
    atomicMax(&g_winner[b.w], base + 8u);
}

// count8 = N_OUT/8 threads, each produces 8 outputs.
__global__ void compact_kernel(float* __restrict__ out,
                               const float* __restrict__ x,
                               int count8) {
    int t = blockIdx.x * blockDim.x + threadIdx.x;
    if (t >= count8) return;

    const uint4* __restrict__ sp = reinterpret_cast<const uint4*>(g_winner);
    float4* __restrict__ op = reinterpret_cast<float4*>(out);

    // Scratch is dead after this read: stream it (evict-first).
    uint4 w0 = __ldcs(&sp[2 * t + 0]);
    uint4 w1 = __ldcs(&sp[2 * t + 1]);

    float4 o0, o1;
    o0.x = w0.x ? __ldg(&x[w0.x - 1u]) : 0.0f;
    o0.y = w0.y ? __ldg(&x[w0.y - 1u]) : 0.0f;
    o0.z = w0.z ? __ldg(&x[w0.z - 1u]) : 0.0f;
    o0.w = w0.w ? __ldg(&x[w0.w - 1u]) : 0.0f;
    o1.x = w1.x ? __ldg(&x[w1.x - 1u]) : 0.0f;
    o1.y = w1.y ? __ldg(&x[w1.y - 1u]) : 0.0f;
    o1.z = w1.z ? __ldg(&x[w1.z - 1u]) : 0.0f;
    o1.w = w1.w ? __ldg(&x[w1.w - 1u]) : 0.0f;

    // out is write-once: streaming store, don't evict x/scratch.
    __stcs(&op[2 * t + 0], o0);
    __stcs(&op[2 * t + 1], o1);
}

extern "C" void kernel_launch(void* const* d_in, const int* in_sizes, int n_in,
                              void* d_out, int out_size) {
    const float* x = reinterpret_cast<const float*>(d_in[0]);
    const int* pos = reinterpret_cast<const int*>(d_in[1]);
    float* out     = reinterpret_cast<float*>(d_out);

    int n = in_sizes[0];             // 6,422,528 (divisible by 8)
    int n8 = n / 8;
    int count16 = out_size / 16;     // 1,605,632
    int count8  = out_size / 8;      // 3,211,264

    const int T = 256;

    // Z: zero the winner scratch (heats it in L2 right before the atomics).
    zero_scratch_kernel<<<(count16 + T - 1) / T, T>>>(count16);

    // S: deterministic last-index-wins via 32-bit atomicMax, 8/thread.
    scatter_kernel<<<(n8 + T - 1) / T, T>>>(
        reinterpret_cast<const int4*>(pos), n8);

    // C: gather winners' values, zero-fill empties, stream out.
    compact_kernel<<<(count8 + T - 1) / T, T>>>(out, x, count8);
}